// round 16
// baseline (speedup 1.0000x reference)
#include <cuda_runtime.h>
#include <cstdint>

#define W_IMG 512
#define H_IMG 512
#define HW    (512*512)
#define NB    4
#define EPS   1e-5f

#define TILE_W 64
#define TILE_H 8
#define BX 32
#define BY 8
#define NTH_C  256                // consumer threads (8 warps)
#define NTH_ALL 288               // + 1 producer warp
#define NWARPS 9
#define PPT 2
#define HALO 2
#define SM_W (TILE_W + 2*HALO)   // 68
#define SM_H (TILE_H + 2*HALO)   // 12

#define NCTA 444                  // 148 SMs x occ 3 — exact fit, all resident
#define NTILES 2048
#define NPROD 128
#define CH_PB (NPROD / NB)

// ring: 4 stages x (5 taps x 8 rows x 64 cols) floats
#define STAGE_FLOATS 2560
#define STAGE_BYTES  10240
#define RING_FLOATS  (4 * STAGE_FLOATS)
#define FGH_FLOATS   (SM_H * SM_W)              // 816
#define DSMEM_FLOATS (RING_FLOATS + 3 * FGH_FLOATS)
#define DSMEM_BYTES  (DSMEM_FLOATS * 4)         // 50752

// named barriers (id 0 reserved for __syncthreads): FULL 1..4, EMPTY 5..8
#define BAR_FULL(s)  ((s) + 1)
#define BAR_EMPTY(s) ((s) + 5)
#define BAR_SYNC(id)   asm volatile("bar.sync %0, %1;"   :: "r"(id), "r"(NTH_ALL) : "memory")
#define BAR_ARRIVE(id) asm volatile("bar.arrive %0, %1;" :: "r"(id), "r"(NTH_ALL) : "memory")
#define CP_WAIT(n)     asm volatile("cp.async.wait_group %0;" :: "n"(n) : "memory")

__device__ float g_gmax_partial[NPROD];
__device__ int   g_count;
__device__ int   g_done;
__device__ int   g_tile;
__device__ float g_blockA[NCTA];
__device__ float g_blockB[NCTA];

// producer: copy one stage (5 tap-rows, 10KB) into ring slot via cp.async
__device__ __forceinline__ void issue_stage(const float* rwbase, int s,
                                            uint32_t ring_smem, int lane) {
    const uint32_t dst0 = ring_smem + (uint32_t)((s & 3) * STAGE_BYTES);
    const float* src0 = rwbase + (size_t)(s * 5) * HW;
#pragma unroll
    for (int it = 0; it < 20; it++) {
        const int q   = lane + it * 32;          // 0..639
        const int j   = q >> 7;                  // tap 0..4
        const int rem = q & 127;
        const int row = rem >> 4;
        const int c4  = rem & 15;
        const float* src = src0 + (size_t)j * HW + row * W_IMG + c4 * 4;
        asm volatile("cp.async.cg.shared.global [%0], [%1], 16;"
                     :: "r"(dst0 + q * 16), "l"(src));
    }
    asm volatile("cp.async.commit_group;" ::: "memory");
}

__global__ __launch_bounds__(NTH_ALL, 3)
void intensity_loss_main(const float* __restrict__ fake,
                         const float* __restrict__ gamma_hdr,
                         const float* __restrict__ hdr_im,
                         const float* __restrict__ r_weights,
                         const float* __restrict__ f_factors,
                         const float* __restrict__ gray,
                         float* __restrict__ out) {
    extern __shared__ __align__(16) float dsm[];
    float* wring = dsm;                       // [4][5][8][64]
    float* sf    = dsm + RING_FLOATS;
    float* sg    = sf + FGH_FLOATS;
    float* sh    = sg + FGH_FLOATS;
    __shared__ float redA[NWARPS], redB[NWARPS];
    __shared__ float s_gmax4[NB];
    __shared__ int   s_last;
    __shared__ int   s_tile;

    const int cta  = blockIdx.x;
    const int tid  = threadIdx.x;
    const int lane = tid & 31;
    const int wid  = tid >> 5;
    const bool is_cons = (tid < NTH_C);
    const uint32_t ring_smem = (uint32_t)__cvta_generic_to_shared(wring);

    // ---- gray-max producers: first NPROD CTAs (all resident: 444 exact) ----
    if (cta < NPROD) {
        const int gb    = cta / CH_PB;
        const int chunk = cta - gb * CH_PB;
        const float4* p4 = reinterpret_cast<const float4*>(gray + (size_t)gb * HW);
        const int base = chunk * 2048;
        float m = 0.0f;
        for (int idx = tid; idx < 2048; idx += NTH_ALL) {
            float4 v = p4[base + idx];
            m = fmaxf(m, fmaxf(fmaxf(v.x, v.y), fmaxf(v.z, v.w)));
        }
#pragma unroll
        for (int o = 16; o > 0; o >>= 1)
            m = fmaxf(m, __shfl_down_sync(0xFFFFFFFFu, m, o));
        if (lane == 0) redA[wid] = m;
        __syncthreads();
        if (tid == 0) {
            float mm = redA[0];
#pragma unroll
            for (int w = 1; w < NWARPS; w++) mm = fmaxf(mm, redA[w]);
            g_gmax_partial[cta] = mm;
            __threadfence();
            atomicAdd(&g_count, 1);
        }
        __syncthreads();
    }

    const int tx = tid & 31;          // consumer lane
    const int ty = wid;               // consumer row (0..7)
    const int lw = tx * PPT;
    const int lh = ty;

    float accA = 0.0f, accB = 0.0f;
    bool gmax_ready = false;
    bool first_tile = true;

    for (;;) {
        __syncthreads();                       // prev tile fully consumed
        if (tid == 0) s_tile = atomicAdd(&g_tile, 1);
        __syncthreads();
        const int s = s_tile;
        if (s >= NTILES) break;

        const int t     = s >> 9;
        const int rem   = s & 511;
        const int wbase = (rem & 7) * TILE_W;
        const int hbase = (rem >> 3) * TILE_H;

        const float ff   = f_factors[t];
        const float expo = 1.0f - ff;

        if (is_cons) {
            // ---- consumers: stage f/g/h tile + halo ----
            const float* fp = fake      + (size_t)t * HW;
            const float* gp = gamma_hdr + (size_t)t * HW;
            const float* hp = hdr_im    + (size_t)t * HW;
            for (int i = tid; i < SM_H * SM_W; i += NTH_C) {
                const int r  = i / SM_W;
                const int c  = i - r * SM_W;
                const int ghh = hbase + r - HALO;
                const int gww = wbase + c - HALO;
                float vf = 0.0f, vg = 0.0f, vh = 0.0f;
                if (ghh >= 0 && ghh < H_IMG && gww >= 0 && gww < W_IMG) {
                    const int gi = ghh * W_IMG + gww;
                    vf = fp[gi];
                    vg = gp[gi];
                    vh = __powf(hp[gi], expo);
                }
                sf[i] = vf; sg[i] = vg; sh[i] = vh;
            }
        } else {
            // ---- producer warp: issue stages 0..3 into the ring ----
            const float* rwbase = r_weights + (size_t)t * 25 * HW
                                  + (size_t)hbase * W_IMG + wbase;
            if (first_tile) {
                issue_stage(rwbase, 0, ring_smem, lane);
                issue_stage(rwbase, 1, ring_smem, lane);
                issue_stage(rwbase, 2, ring_smem, lane);
                issue_stage(rwbase, 3, ring_smem, lane);
            } else {
                BAR_SYNC(BAR_EMPTY(0)); issue_stage(rwbase, 0, ring_smem, lane);
                BAR_SYNC(BAR_EMPTY(1)); issue_stage(rwbase, 1, ring_smem, lane);
                BAR_SYNC(BAR_EMPTY(2)); issue_stage(rwbase, 2, ring_smem, lane);
                BAR_SYNC(BAR_EMPTY(3)); issue_stage(rwbase, 3, ring_smem, lane);
            }
            CP_WAIT(3);                 // stage 0 landed
            BAR_ARRIVE(BAR_FULL(0));
        }
        first_tile = false;
        __syncthreads();                // f/g/h staged; ring protocol continues

        if (is_cons) {
            // ---- consumer mainloop: weights from smem ring, zero LDG ----
            float s1f[PPT] = {0,0}, s2f[PPT] = {0,0};
            float s1g[PPT] = {0,0}, s2g[PPT] = {0,0};
            float s1h[PPT] = {0,0}, ws [PPT] = {0,0};

#pragma unroll
            for (int di = 0; di < 5; di++) {
                const int slot = di & 3;
                BAR_SYNC(BAR_FULL(slot));       // wait stage di's data

                const float* wst = wring + slot * STAGE_FLOATS + ty * 64 + lw;
                float2 wv[5];
#pragma unroll
                for (int j = 0; j < 5; j++)
                    wv[j] = *reinterpret_cast<const float2*>(wst + j * 512);

                const int rowoff = (lh + di) * SM_W + lw;
                const float2 f0 = *reinterpret_cast<const float2*>(&sf[rowoff]);
                const float2 f1 = *reinterpret_cast<const float2*>(&sf[rowoff + 2]);
                const float2 f2 = *reinterpret_cast<const float2*>(&sf[rowoff + 4]);
                const float2 g0 = *reinterpret_cast<const float2*>(&sg[rowoff]);
                const float2 g1 = *reinterpret_cast<const float2*>(&sg[rowoff + 2]);
                const float2 g2 = *reinterpret_cast<const float2*>(&sg[rowoff + 4]);
                const float2 h0 = *reinterpret_cast<const float2*>(&sh[rowoff]);
                const float2 h1 = *reinterpret_cast<const float2*>(&sh[rowoff + 2]);
                const float2 h2 = *reinterpret_cast<const float2*>(&sh[rowoff + 4]);
                const float xf[6] = {f0.x, f0.y, f1.x, f1.y, f2.x, f2.y};
                const float xg[6] = {g0.x, g0.y, g1.x, g1.y, g2.x, g2.y};
                const float xh[6] = {h0.x, h0.y, h1.x, h1.y, h2.x, h2.y};

#pragma unroll
                for (int dj = 0; dj < 5; dj++) {
                    const float rwa[PPT] = {wv[dj].x, wv[dj].y};
#pragma unroll
                    for (int l = 0; l < PPT; l++) {
                        const float w = rwa[l];
                        ws[l] += w;
                        const float a = xf[dj + l];
                        const float wa = w * a;
                        s1f[l] += wa;
                        s2f[l] = fmaf(wa, a, s2f[l]);
                        const float gq = xg[dj + l];
                        const float wg = w * gq;
                        s1g[l] += wg;
                        s2g[l] = fmaf(wg, gq, s2g[l]);
                        s1h[l] = fmaf(w, xh[dj + l], s1h[l]);
                    }
                }
                BAR_ARRIVE(BAR_EMPTY(slot));    // stage consumed
            }

            // lazy gray-max wait (producers long done; first tile only)
            if (!gmax_ready) {
                if (tid == 0) {
                    while (*(volatile int*)&g_count < NPROD) { }
                }
                gmax_ready = true;
            }

            // stash partial sums; finish after the all-thread sync below
            // epilogue math done here (cobj needs s_gmax4 — set below at t sync)
            // To keep ordering simple, compute epilogue after the gmax publish:
            // store accumulators to locals and fall through.
            // (gmax publish happens in the all-threads region below)
            // -- epilogue moved below --
            // save per-pixel stats in registers across the sync (they live on)
            // handled by scope: do epilogue after shared publish
            {
                // publish gmax (once) — needs a block sync; do cheap every tile
            }
            // defer: see post-sync epilogue
            // (fallthrough)
            // NOTE: we need cobj; compute after __syncthreads below.
            // Stash into registers:
            float l_s1f0 = s1f[0], l_s1f1 = s1f[1];
            float l_s2f0 = s2f[0], l_s2f1 = s2f[1];
            float l_s1g0 = s1g[0], l_s1g1 = s1g[1];
            float l_s2g0 = s2g[0], l_s2g1 = s2g[1];
            float l_s1h0 = s1h[0], l_s1h1 = s1h[1];
            float l_ws0  = ws[0],  l_ws1  = ws[1];

            // gmax publish: one warp reduces partials into s_gmax4 (idempotent)
            if (tid < 32) {
#pragma unroll
                for (int bb = 0; bb < NB; bb++) {
                    float m = g_gmax_partial[bb * CH_PB + tid];
#pragma unroll
                    for (int o = 16; o > 0; o >>= 1)
                        m = fmaxf(m, __shfl_down_sync(0xFFFFFFFFu, m, o));
                    if (tid == 0) s_gmax4[bb] = m;
                }
            }
            asm volatile("bar.sync 9, %0;" :: "r"(NTH_C) : "memory");  // consumers only

            const float cobj = s_gmax4[t] / ff;   // ALPHA = 1
            const float sw1[PPT] = {l_ws0, l_ws1};
            const float sa1f[PPT] = {l_s1f0, l_s1f1}, sa2f[PPT] = {l_s2f0, l_s2f1};
            const float sa1g[PPT] = {l_s1g0, l_s1g1}, sa2g[PPT] = {l_s2g0, l_s2g1};
            const float sa1h[PPT] = {l_s1h0, l_s1h1};
#pragma unroll
            for (int l = 0; l < PPT; l++) {
                const float wsl  = sw1[l];
                const float inv  = 1.0f / wsl;
                const float muf  = sa1f[l] * inv;
                const float vrf  = fmaxf(sa2f[l] * inv - muf * muf, 0.0f);
                const float stdf = sqrtf(vrf + EPS);
                const float mug  = sa1g[l] * inv;
                const float vrg  = fmaxf(sa2g[l] * inv - mug * mug, 0.0f);
                const float stdg = sqrtf(vrg + EPS);
                const float muh  = sa1h[l] * inv;
                const float obj  = cobj * stdg * (muh + EPS);
                const float r    = 1.0f - stdf / (stdf + obj);
                const float wblf = wsl - 1.0f;
                accA = fmaf(r, wblf, accA);
                accB += wblf;
            }
        } else {
            // ---- producer region B: keep the ring ahead of consumption ----
            const float* rwbase = r_weights + (size_t)t * 25 * HW
                                  + (size_t)hbase * W_IMG + wbase;
            CP_WAIT(2); BAR_ARRIVE(BAR_FULL(1));            // s1 landed
            CP_WAIT(1); BAR_ARRIVE(BAR_FULL(2));            // s2 landed
            BAR_SYNC(BAR_EMPTY(0));                         // s0 consumed
            issue_stage(rwbase, 4, ring_smem, lane);
            CP_WAIT(1); BAR_ARRIVE(BAR_FULL(3));            // s3 landed
            CP_WAIT(0); BAR_ARRIVE(BAR_FULL(0));            // s4 landed
        }
    }

    // ---- block reduction over all tiles this CTA processed ----
#pragma unroll
    for (int o = 16; o > 0; o >>= 1) {
        accA += __shfl_down_sync(0xFFFFFFFFu, accA, o);
        accB += __shfl_down_sync(0xFFFFFFFFu, accB, o);
    }
    if (lane == 0) { redA[wid] = accA; redB[wid] = accB; }
    __syncthreads();
    if (wid == 0) {
        accA = (lane < NWARPS) ? redA[lane] : 0.0f;
        accB = (lane < NWARPS) ? redB[lane] : 0.0f;
#pragma unroll
        for (int o = 8; o > 0; o >>= 1) {
            accA += __shfl_down_sync(0xFFFFFFFFu, accA, o);
            accB += __shfl_down_sync(0xFFFFFFFFu, accB, o);
        }
        if (lane == 0) {
            g_blockA[cta] = accA;
            g_blockB[cta] = accB;
        }
    }

    // ---- last-block-done election: single-kernel finalize ----
    __threadfence();
    if (tid == 0) s_last = atomicAdd(&g_done, 1);
    __syncthreads();
    if (s_last == NCTA - 1) {
        float a = 0.0f, bsum = 0.0f;
        for (int i = tid; i < NCTA; i += NTH_ALL) {
            a    += g_blockA[i];
            bsum += g_blockB[i];
        }
#pragma unroll
        for (int o = 16; o > 0; o >>= 1) {
            a    += __shfl_down_sync(0xFFFFFFFFu, a, o);
            bsum += __shfl_down_sync(0xFFFFFFFFu, bsum, o);
        }
        if (lane == 0) { redA[wid] = a; redB[wid] = bsum; }
        __syncthreads();
        if (wid == 0) {
            a    = (lane < NWARPS) ? redA[lane] : 0.0f;
            bsum = (lane < NWARPS) ? redB[lane] : 0.0f;
#pragma unroll
            for (int o = 8; o > 0; o >>= 1) {
                a    += __shfl_down_sync(0xFFFFFFFFu, a, o);
                bsum += __shfl_down_sync(0xFFFFFFFFu, bsum, o);
            }
            if (lane == 0) {
                out[0] = a / bsum;
                g_done  = 0;
                g_count = 0;
                g_tile  = 0;
            }
        }
    }
}

extern "C" void kernel_launch(void* const* d_in, const int* in_sizes, int n_in,
                              void* d_out, int out_size) {
    const float* fake      = (const float*)d_in[0];
    const float* gamma_hdr = (const float*)d_in[1];
    const float* hdr_im    = (const float*)d_in[2];
    const float* r_weights = (const float*)d_in[3];
    const float* f_factors = (const float*)d_in[4];
    const float* gray      = (const float*)d_in[5];
    float* out = (float*)d_out;

    static int configured = 0;
    if (!configured) {
        cudaFuncSetAttribute(intensity_loss_main,
                             cudaFuncAttributeMaxDynamicSharedMemorySize,
                             DSMEM_BYTES);
        configured = 1;
    }

    intensity_loss_main<<<NCTA, NTH_ALL, DSMEM_BYTES>>>(
        fake, gamma_hdr, hdr_im, r_weights, f_factors, gray, out);
}